// round 6
// baseline (speedup 1.0000x reference)
#include <cuda_runtime.h>
#include <cuda_bf16.h>
#include <cstdint>
#include <cstddef>

// VectorQuantizer, two-phase with in-flight candidate collection:
//   Phase 1: bf16 ldmatrix+mma GEMM; per-row running screen min in smem;
//            candidates (s <= runmin + MARGIN) appended to per-row lists.
//   Phase 2: prune candidates vs final min, exact fp32 rescue
//            (bit-identical to the passing Round-2 chain), first-index ties.
// Output: [ z_q_st (B*512) | indices as float (B) | vq_loss (1) ]

#define DDIM 512
#define NB 16384
#define NK 8192
#define BM 128
#define BN 128
#define SA 40              // smem row stride in halves (80B: conflict-free LDSM)
#define CAP 64
#define MARGIN 2e-3f

__device__ float  g_ee[NK];
__device__ float  g_zz[NB];
__device__ float  g_rmin[NB];
__device__ int    g_best[NB];
__device__ double g_part[512];
__device__ __nv_bfloat16 g_zb[NB * DDIM];
__device__ __nv_bfloat16 g_eb[NK * DDIM];
__device__ int    g_ccnt[NB];
__device__ int    g_ck[NB * CAP];
__device__ float  g_cs[NB * CAP];

// ---- helpers -------------------------------------------------------------
__device__ __forceinline__ unsigned smem_u32(const void* p)
{
    return (unsigned)__cvta_generic_to_shared(p);
}
__device__ __forceinline__ void cp16(__nv_bfloat16* sdst, const void* gsrc)
{
    asm volatile("cp.async.ca.shared.global [%0], [%1], 16;\n"
                 :: "r"(smem_u32(sdst)), "l"(gsrc));
}
__device__ __forceinline__ void cp_commit() { asm volatile("cp.async.commit_group;\n"); }
__device__ __forceinline__ void cp_wait0()  { asm volatile("cp.async.wait_group 0;\n"); }

__device__ __forceinline__ void ldsm4(unsigned* r, unsigned addr)
{
    asm volatile("ldmatrix.sync.aligned.m8n8.x4.shared.b16 {%0,%1,%2,%3}, [%4];"
                 : "=r"(r[0]), "=r"(r[1]), "=r"(r[2]), "=r"(r[3]) : "r"(addr));
}
__device__ __forceinline__ void mma_bf16(float* c, const unsigned* a,
                                         unsigned b0, unsigned b1)
{
    asm volatile(
        "mma.sync.aligned.m16n8k16.row.col.f32.bf16.bf16.f32 "
        "{%0,%1,%2,%3}, {%4,%5,%6,%7}, {%8,%9}, {%0,%1,%2,%3};\n"
        : "+f"(c[0]), "+f"(c[1]), "+f"(c[2]), "+f"(c[3])
        : "r"(a[0]), "r"(a[1]), "r"(a[2]), "r"(a[3]), "r"(b0), "r"(b1));
}

// order-preserving float<->uint encode for atomicMin
__device__ __forceinline__ unsigned fenc(float f)
{
    unsigned u = __float_as_uint(f);
    return (u & 0x80000000u) ? ~u : (u | 0x80000000u);
}
__device__ __forceinline__ float fdec(unsigned u)
{
    return (u & 0x80000000u) ? __uint_as_float(u & 0x7FFFFFFFu)
                             : __uint_as_float(~u);
}

// ---- prep kernels --------------------------------------------------------
__global__ void to_bf16_kernel(const float* __restrict__ src,
                               __nv_bfloat16* __restrict__ dst, int n4)
{
    int i = blockIdx.x * blockDim.x + threadIdx.x;
    if (i >= n4) return;
    float4 v = ((const float4*)src)[i];
    __nv_bfloat162 p0 = __floats2bfloat162_rn(v.x, v.y);
    __nv_bfloat162 p1 = __floats2bfloat162_rn(v.z, v.w);
    uint2 w;
    w.x = *reinterpret_cast<unsigned*>(&p0);
    w.y = *reinterpret_cast<unsigned*>(&p1);
    ((uint2*)dst)[i] = w;
}

__global__ void rowsq_kernel(const float* __restrict__ emb,
                             const float* __restrict__ z,
                             int K, int B)
{
    int w    = (blockIdx.x * blockDim.x + threadIdx.x) >> 5;
    int lane = threadIdx.x & 31;
    if (w >= K + B) return;
    const float* src = (w < K) ? (emb + (size_t)w * DDIM)
                               : (z   + (size_t)(w - K) * DDIM);
    float s = 0.f;
#pragma unroll
    for (int t = 0; t < DDIM / 32; t++) {
        float x = src[lane + 32 * t];
        s = fmaf(x, x, s);
    }
#pragma unroll
    for (int off = 16; off > 0; off >>= 1)
        s += __shfl_xor_sync(0xFFFFFFFFu, s, off);
    if (lane == 0) {
        if (w < K) g_ee[w] = s;
        else       g_zz[w - K] = s;
    }
}

__global__ void zero_cnt_kernel(int n)
{
    int i = blockIdx.x * blockDim.x + threadIdx.x;
    if (i < n) g_ccnt[i] = 0;
}

// ---- Phase 1: bf16 GEMM screen + in-flight candidate collection ----------
// 512 threads = 16 warps (4 warpM x 4 warpN); block 128x128, warp 32x32.
__global__ __launch_bounds__(512, 1)
void vq_phase1_kernel(int K)
{
    __shared__ __nv_bfloat16 sA[2][BM][SA];
    __shared__ __nv_bfloat16 sB[2][BN][SA];
    __shared__ float    sEE[BN];
    __shared__ unsigned sRun[BM];

    const int tid   = threadIdx.x;
    const int wid   = tid >> 5;
    const int lane  = tid & 31;
    const int g     = lane >> 2;
    const int t     = lane & 3;
    const int warpM = wid >> 2;
    const int warpN = wid & 3;
    const int brow  = blockIdx.x * BM;

    if (tid < BM) sRun[tid] = 0xFFFFFFFFu;

    // cp.async mapping: 128 rows x 4 chunks of 16B per operand, 1 per thread
    const int cr = tid >> 2;
    const int cc = (tid & 3) * 8;

    // ldmatrix lane offsets
    const int aRow = lane & 15;
    const int aCol = (lane >> 4) << 3;
    const int bRow = (lane & 7) + ((lane & 16) >> 1);
    const int bCol = lane & 8;

    const int NCH = (K / BN) * (DDIM / 32);   // 1024

    // prologue: chunk 0 -> buffer 0
    cp16(&sA[0][cr][cc], g_zb + (size_t)(brow + cr) * DDIM + cc);
    cp16(&sB[0][cr][cc], g_eb + (size_t)cr * DDIM + cc);
    cp_commit();

    float acc[2][4][4];
#pragma unroll
    for (int mt = 0; mt < 2; mt++)
#pragma unroll
        for (int nt = 0; nt < 4; nt++)
#pragma unroll
            for (int r = 0; r < 4; r++) acc[mt][nt][r] = 0.f;

    for (int c = 0; c < NCH; c++) {
        const int dch = c & 15;
        const int kt  = (c >> 4) * BN;
        const int cur = c & 1;

        cp_wait0();
        __syncthreads();

        if (dch == 0 && tid < BN) sEE[tid] = g_ee[kt + tid];

        if (c + 1 < NCH) {
            const int ndb = ((c + 1) & 15) * 32;
            const int nkt = ((c + 1) >> 4) * BN;
            const int nb  = (c + 1) & 1;
            cp16(&sA[nb][cr][cc], g_zb + (size_t)(brow + cr) * DDIM + ndb + cc);
            cp16(&sB[nb][cr][cc], g_eb + (size_t)(nkt + cr) * DDIM + ndb + cc);
            cp_commit();
        }

        // compute: 2 k16 steps
#pragma unroll
        for (int ks = 0; ks < 2; ks++) {
            const int kb = ks * 16;
            unsigned A[2][4], Bf[2][4];
#pragma unroll
            for (int mt = 0; mt < 2; mt++)
                ldsm4(A[mt], smem_u32(&sA[cur][warpM * 32 + mt * 16 + aRow][kb + aCol]));
#pragma unroll
            for (int np = 0; np < 2; np++)
                ldsm4(Bf[np], smem_u32(&sB[cur][warpN * 32 + np * 16 + bRow][kb + bCol]));
#pragma unroll
            for (int mt = 0; mt < 2; mt++)
#pragma unroll
                for (int nt = 0; nt < 4; nt++)
                    mma_bf16(acc[mt][nt], A[mt],
                             Bf[nt >> 1][(nt & 1) * 2], Bf[nt >> 1][(nt & 1) * 2 + 1]);
        }

        if (dch == 15) {
            // s = ee - 2G for all 32 values
            float s[2][4][4];
#pragma unroll
            for (int mt = 0; mt < 2; mt++)
#pragma unroll
                for (int nt = 0; nt < 4; nt++)
#pragma unroll
                    for (int r = 0; r < 4; r++) {
                        int col = warpN * 32 + nt * 8 + 2 * t + (r & 1);
                        s[mt][nt][r] = fmaf(-2.f, acc[mt][nt][r], sEE[col]);
                    }
            // per-row mins -> smem running min (atomicMin, order-encoded)
#pragma unroll
            for (int mt = 0; mt < 2; mt++)
#pragma unroll
                for (int h = 0; h < 2; h++) {
                    float m = 3.4e38f;
#pragma unroll
                    for (int nt = 0; nt < 4; nt++) {
                        float a0 = s[mt][nt][h * 2 + 0];
                        float a1 = s[mt][nt][h * 2 + 1];
                        float mm = (a0 < a1) ? a0 : a1;
                        if (mm < m) m = mm;
                    }
                    float om = __shfl_xor_sync(0xFFFFFFFFu, m, 1);
                    if (om < m) m = om;
                    om = __shfl_xor_sync(0xFFFFFFFFu, m, 2);
                    if (om < m) m = om;
                    if (t == 0)
                        atomicMin(&sRun[warpM * 32 + mt * 16 + h * 8 + g], fenc(m));
                }
            __syncthreads();
            // append candidates vs updated running threshold
#pragma unroll
            for (int mt = 0; mt < 2; mt++)
#pragma unroll
                for (int h = 0; h < 2; h++) {
                    int   row = warpM * 32 + mt * 16 + h * 8 + g;
                    float th  = fdec(sRun[row]) + MARGIN;
#pragma unroll
                    for (int nt = 0; nt < 4; nt++)
#pragma unroll
                        for (int c2 = 0; c2 < 2; c2++) {
                            float sv = s[mt][nt][h * 2 + c2];
                            if (sv <= th) {
                                int grow = brow + row;
                                int pos  = atomicAdd(&g_ccnt[grow], 1);
                                if (pos < CAP) {
                                    g_ck[grow * CAP + pos] = kt + warpN * 32 + nt * 8 + 2 * t + c2;
                                    g_cs[grow * CAP + pos] = sv;
                                }
                            }
                        }
                }
            // reset accumulators
#pragma unroll
            for (int mt = 0; mt < 2; mt++)
#pragma unroll
                for (int nt = 0; nt < 4; nt++)
#pragma unroll
                    for (int r = 0; r < 4; r++) acc[mt][nt][r] = 0.f;
        }
    }

    __syncthreads();
    if (tid < BM) g_rmin[brow + tid] = fdec(sRun[tid]);
}

// ---- Phase 2: exact fp32 rescue on candidates ----------------------------
__global__ __launch_bounds__(256)
void rescue_kernel(const float* __restrict__ z,
                   const float* __restrict__ emb, int K)
{
    const int wid  = threadIdx.x >> 5;
    const int lane = threadIdx.x & 31;
    const int row  = blockIdx.x * 8 + wid;

    const int   cnt    = g_ccnt[row];
    const float thresh = g_rmin[row] + MARGIN;
    const float zz     = g_zz[row];
    const float4* zp   = (const float4*)(z + (size_t)row * DDIM);

    float v  = 3.4e38f;
    int   bi = 0x7FFFFFFF;

    if (cnt <= CAP) {
        for (int ci = lane; ci < cnt; ci += 32) {
            float sv = g_cs[row * CAP + ci];
            if (sv <= thresh) {
                int k = g_ck[row * CAP + ci];
                const float4* ep = (const float4*)(emb + (size_t)k * DDIM);
                float accd = 0.f;
#pragma unroll 4
                for (int d = 0; d < DDIM / 4; d++) {
                    float4 za = zp[d], ea = ep[d];
                    accd = fmaf(za.x, ea.x, accd);
                    accd = fmaf(za.y, ea.y, accd);
                    accd = fmaf(za.z, ea.z, accd);
                    accd = fmaf(za.w, ea.w, accd);
                }
                float q = fmaf(-2.f, accd, zz) + g_ee[k];
                if (q < v || (q == v && k < bi)) { v = q; bi = k; }
            }
        }
    } else {
        // overflow fallback: exact scan over all k (statistically unreachable)
        for (int k = lane; k < K; k += 32) {
            const float4* ep = (const float4*)(emb + (size_t)k * DDIM);
            float accd = 0.f;
#pragma unroll 4
            for (int d = 0; d < DDIM / 4; d++) {
                float4 za = zp[d], ea = ep[d];
                accd = fmaf(za.x, ea.x, accd);
                accd = fmaf(za.y, ea.y, accd);
                accd = fmaf(za.z, ea.z, accd);
                accd = fmaf(za.w, ea.w, accd);
            }
            float q = fmaf(-2.f, accd, zz) + g_ee[k];
            if (q < v || (q == v && k < bi)) { v = q; bi = k; }
        }
    }
#pragma unroll
    for (int off = 16; off > 0; off >>= 1) {
        float ov = __shfl_xor_sync(0xFFFFFFFFu, v, off);
        int   oi = __shfl_xor_sync(0xFFFFFFFFu, bi, off);
        if (ov < v || (ov == v && oi < bi)) { v = ov; bi = oi; }
    }
    if (lane == 0) g_best[row] = bi;
}

// ---- output + loss -------------------------------------------------------
__global__ void gather_loss_kernel(const float* __restrict__ z,
                                   const float* __restrict__ emb,
                                   float* __restrict__ out_zq,
                                   float* __restrict__ out_idx,
                                   int B)
{
    __shared__ double sred[128];
    const int tid = threadIdx.x;
    double lsum = 0.0;

    for (int r = 0; r < 32; r++) {
        int b   = blockIdx.x * 32 + r;
        int idx = g_best[b];
        if (tid == 0 && out_idx) out_idx[b] = (float)idx;

        float4 zv = ((const float4*)(z   + (size_t)b   * DDIM))[tid];
        float4 ev = ((const float4*)(emb + (size_t)idx * DDIM))[tid];
        float4 o;
        float dx;
        dx = ev.x - zv.x; o.x = zv.x + dx; lsum += (double)dx * (double)dx;
        dx = ev.y - zv.y; o.y = zv.y + dx; lsum += (double)dx * (double)dx;
        dx = ev.z - zv.z; o.z = zv.z + dx; lsum += (double)dx * (double)dx;
        dx = ev.w - zv.w; o.w = zv.w + dx; lsum += (double)dx * (double)dx;
        ((float4*)(out_zq + (size_t)b * DDIM))[tid] = o;
    }

    sred[tid] = lsum;
    __syncthreads();
#pragma unroll
    for (int s = 64; s > 0; s >>= 1) {
        if (tid < s) sred[tid] += sred[tid + s];
        __syncthreads();
    }
    if (tid == 0) g_part[blockIdx.x] = sred[0];
}

__global__ void finalize_kernel(float* __restrict__ out_loss, int nparts, double scale)
{
    double s = 0.0;
    for (int i = 0; i < nparts; i++) s += g_part[i];
    *out_loss = (float)(s * scale);
}

// -------------------------------------------------------------------------
extern "C" void kernel_launch(void* const* d_in, const int* in_sizes, int n_in,
                              void* d_out, int out_size)
{
    const float* z   = (const float*)d_in[0];
    const float* emb = (const float*)d_in[1];
    int B = in_sizes[0] / DDIM;   // 16384
    int K = in_sizes[1] / DDIM;   // 8192

    float* out      = (float*)d_out;
    float* out_zq   = out;
    float* out_idx  = ((size_t)out_size >= (size_t)B * DDIM + (size_t)B)
                        ? out + (size_t)B * DDIM : nullptr;
    float* out_loss = ((size_t)out_size >= (size_t)B * DDIM + (size_t)B + 1)
                        ? out + (size_t)B * DDIM + B : nullptr;

    __nv_bfloat16 *zb, *eb;
    cudaGetSymbolAddress((void**)&zb, g_zb);
    cudaGetSymbolAddress((void**)&eb, g_eb);

    int nz4 = B * DDIM / 4, ne4 = K * DDIM / 4;
    to_bf16_kernel<<<(nz4 + 255) / 256, 256>>>(z, zb, nz4);
    to_bf16_kernel<<<(ne4 + 255) / 256, 256>>>(emb, eb, ne4);
    rowsq_kernel<<<((K + B) * 32 + 255) / 256, 256>>>(emb, z, K, B);
    zero_cnt_kernel<<<(B + 255) / 256, 256>>>(B);

    vq_phase1_kernel<<<B / BM, 512>>>(K);
    rescue_kernel<<<B / 8, 256>>>(z, emb, K);

    int gblocks = B / 32;
    gather_loss_kernel<<<gblocks, 128>>>(z, emb, out_zq, out_idx, B);
    if (out_loss)
        finalize_kernel<<<1, 1>>>(out_loss, gblocks, 1.25 / ((double)B * (double)DDIM));
}

// round 7
// speedup vs baseline: 5.3385x; 5.3385x over previous
#include <cuda_runtime.h>
#include <cuda_bf16.h>
#include <cuda_fp16.h>
#include <cstdint>
#include <cstddef>

// VectorQuantizer, two-phase:
//   Phase 1: bf16 ldmatrix+mma GEMM -> fp16 screen s[b,k] = ee - 2*G (256 MB)
//            + per-row fp32 min (hot loop identical to the 824us R5 kernel,
//            feeds upgraded from scalar LDS to ldmatrix.x4).
//   Phase 2: per-row block scan of the screen (final-min threshold) -> compact
//            candidates -> exact fp32 rescue with the bit-identical Round-2
//            serial fmaf chain; deterministic min with first-index ties.
// Output: [ z_q_st (B*512) | indices as float (B) | vq_loss (1) ]

#define DDIM 512
#define NB 16384
#define NK 8192
#define BM 128
#define BN 128

#define SA 40                    // smem row stride in halves (80B, LDSM conflict-free)
#define ABUF_H (128 * SA)
#define BUF_H  (2 * ABUF_H)
#define STAGE_OFF_H (2 * BUF_H)
#define STROW_H 136

#define CAP 64
#define MARGIN 2e-3f

__device__ float  g_ee[NK];
__device__ float  g_zz[NB];
__device__ float  g_rmin[NB];
__device__ int    g_best[NB];
__device__ double g_part[512];

__device__ __nv_bfloat16 g_zb[NB * DDIM];
__device__ __nv_bfloat16 g_eb[NK * DDIM];
__device__ __half        g_s[(size_t)NB * NK];  // fp16 screen, 256 MB

// ---- helpers -------------------------------------------------------------
__device__ __forceinline__ unsigned smem_u32(const void* p)
{
    return (unsigned)__cvta_generic_to_shared(p);
}
__device__ __forceinline__ void cp16(__half* sdst, const void* gsrc)
{
    asm volatile("cp.async.ca.shared.global [%0], [%1], 16;\n"
                 :: "r"(smem_u32(sdst)), "l"(gsrc));
}
__device__ __forceinline__ void cp_commit() { asm volatile("cp.async.commit_group;\n"); }
__device__ __forceinline__ void cp_wait0()  { asm volatile("cp.async.wait_group 0;\n"); }

__device__ __forceinline__ void ldsm4(unsigned* r, unsigned addr)
{
    asm volatile("ldmatrix.sync.aligned.m8n8.x4.shared.b16 {%0,%1,%2,%3}, [%4];"
                 : "=r"(r[0]), "=r"(r[1]), "=r"(r[2]), "=r"(r[3]) : "r"(addr));
}
__device__ __forceinline__ void mma_bf16(float* c, const unsigned* a,
                                         unsigned b0, unsigned b1)
{
    asm volatile(
        "mma.sync.aligned.m16n8k16.row.col.f32.bf16.bf16.f32 "
        "{%0,%1,%2,%3}, {%4,%5,%6,%7}, {%8,%9}, {%0,%1,%2,%3};\n"
        : "+f"(c[0]), "+f"(c[1]), "+f"(c[2]), "+f"(c[3])
        : "r"(a[0]), "r"(a[1]), "r"(a[2]), "r"(a[3]), "r"(b0), "r"(b1));
}

// ---- prep ----------------------------------------------------------------
__global__ void to_bf16_kernel(const float* __restrict__ src,
                               __nv_bfloat16* __restrict__ dst, int n4)
{
    int i = blockIdx.x * blockDim.x + threadIdx.x;
    if (i >= n4) return;
    float4 v = ((const float4*)src)[i];
    __nv_bfloat162 p0 = __floats2bfloat162_rn(v.x, v.y);
    __nv_bfloat162 p1 = __floats2bfloat162_rn(v.z, v.w);
    uint2 w;
    w.x = *reinterpret_cast<unsigned*>(&p0);
    w.y = *reinterpret_cast<unsigned*>(&p1);
    ((uint2*)dst)[i] = w;
}

__global__ void rowsq_kernel(const float* __restrict__ emb,
                             const float* __restrict__ z,
                             int K, int B)
{
    int w    = (blockIdx.x * blockDim.x + threadIdx.x) >> 5;
    int lane = threadIdx.x & 31;
    if (w >= K + B) return;
    const float* src = (w < K) ? (emb + (size_t)w * DDIM)
                               : (z   + (size_t)(w - K) * DDIM);
    float s = 0.f;
#pragma unroll
    for (int t = 0; t < DDIM / 32; t++) {
        float x = src[lane + 32 * t];
        s = fmaf(x, x, s);
    }
#pragma unroll
    for (int off = 16; off > 0; off >>= 1)
        s += __shfl_xor_sync(0xFFFFFFFFu, s, off);
    if (lane == 0) {
        if (w < K) g_ee[w] = s;
        else       g_zz[w - K] = s;
    }
}

// ---- Phase 1 (R5 structure + ldmatrix feeds) -----------------------------
// 256 threads = 8 warps (4 warpM x 2 warpN); block 128x128, warp 32x64.
__global__ __launch_bounds__(256, 1)
void vq_phase1_kernel(int K)
{
    extern __shared__ __half smem[];
    __shared__ float sEE[BN];

    const int tid   = threadIdx.x;
    const int wid   = tid >> 5;
    const int lane  = tid & 31;
    const int g     = lane >> 2;
    const int t     = lane & 3;
    const int warpM = wid >> 1;      // 0..3
    const int warpN = wid & 1;       // 0..1
    const int brow  = blockIdx.x * BM;

    float bestv[4];
#pragma unroll
    for (int a = 0; a < 4; a++) bestv[a] = 3.4e38f;

    // cp.async mapping: 128 rows x 4 chunks of 16B per operand; 2 per thread
    int cp_r[2], cp_c[2];
#pragma unroll
    for (int i = 0; i < 2; i++) {
        int idx = tid + i * 256;
        cp_r[i] = idx >> 2;
        cp_c[i] = (idx & 3) * 8;
    }

    // ldmatrix lane offsets (validated in R6)
    const int aRow = lane & 15;
    const int aCol = (lane >> 4) << 3;
    const int bRow = (lane & 7) + ((lane & 16) >> 1);
    const int bCol = lane & 8;

    const int NCH = (K / BN) * (DDIM / 32);   // 1024

    // prologue: chunk 0 -> buffer 0
    {
        __half* bA = smem;
        __half* bB = smem + ABUF_H;
#pragma unroll
        for (int i = 0; i < 2; i++) {
            cp16(bA + cp_r[i] * SA + cp_c[i],
                 g_zb + (size_t)(brow + cp_r[i]) * DDIM + cp_c[i]);
            cp16(bB + cp_r[i] * SA + cp_c[i],
                 g_eb + (size_t)cp_r[i] * DDIM + cp_c[i]);
        }
        cp_commit();
    }

    float acc[2][8][4];
#pragma unroll
    for (int mt = 0; mt < 2; mt++)
#pragma unroll
        for (int nt = 0; nt < 8; nt++)
#pragma unroll
            for (int r = 0; r < 4; r++) acc[mt][nt][r] = 0.f;

    for (int c = 0; c < NCH; c++) {
        const int dch = c & 15;
        const int kt  = (c >> 4) * BN;
        __half* bA = smem + (c & 1) * BUF_H;
        __half* bB = bA + ABUF_H;

        cp_wait0();
        __syncthreads();

        if (dch == 0 && tid < BN) sEE[tid] = g_ee[kt + tid];

        if (c + 1 < NCH) {
            const int ndb = ((c + 1) & 15) * 32;
            const int nkt = ((c + 1) >> 4) * BN;
            __half* nA = smem + ((c + 1) & 1) * BUF_H;
            __half* nB = nA + ABUF_H;
#pragma unroll
            for (int i = 0; i < 2; i++) {
                cp16(nA + cp_r[i] * SA + cp_c[i],
                     g_zb + (size_t)(brow + cp_r[i]) * DDIM + ndb + cp_c[i]);
                cp16(nB + cp_r[i] * SA + cp_c[i],
                     g_eb + (size_t)(nkt + cp_r[i]) * DDIM + ndb + cp_c[i]);
            }
            cp_commit();
        }

        // compute: 2 k16 steps, ldmatrix feeds
#pragma unroll
        for (int ks = 0; ks < 2; ks++) {
            const int kb = ks * 16;
            unsigned A[2][4], Bf[4][4];
#pragma unroll
            for (int mt = 0; mt < 2; mt++)
                ldsm4(A[mt], smem_u32(&bA[(warpM * 32 + mt * 16 + aRow) * SA + kb + aCol]));
#pragma unroll
            for (int np = 0; np < 4; np++)
                ldsm4(Bf[np], smem_u32(&bB[(warpN * 64 + np * 16 + bRow) * SA + kb + bCol]));
#pragma unroll
            for (int mt = 0; mt < 2; mt++)
#pragma unroll
                for (int nt = 0; nt < 8; nt++)
                    mma_bf16(acc[mt][nt], A[mt],
                             Bf[nt >> 1][(nt & 1) * 2], Bf[nt >> 1][(nt & 1) * 2 + 1]);
        }

        if (dch == 15) {
            __half* stage = smem + STAGE_OFF_H;
#pragma unroll
            for (int mt = 0; mt < 2; mt++)
#pragma unroll
                for (int i = 0; i < 2; i++) {
                    const int a = mt * 2 + i;
                    const int srow = warpM * 32 + mt * 16 + i * 8 + g;
                    float v = 3.4e38f;
#pragma unroll
                    for (int nt = 0; nt < 8; nt++) {
                        int col = warpN * 64 + nt * 8 + 2 * t;
                        float s0 = fmaf(-2.f, acc[mt][nt][i * 2 + 0], sEE[col]);
                        float s1 = fmaf(-2.f, acc[mt][nt][i * 2 + 1], sEE[col + 1]);
                        *(__half2*)&stage[srow * STROW_H + col] =
                            __floats2half2_rn(s0, s1);
                        float m = (s0 < s1) ? s0 : s1;
                        if (m < v) v = m;
                    }
#pragma unroll
                    for (int off = 1; off < 4; off <<= 1) {
                        float ov = __shfl_xor_sync(0xFFFFFFFFu, v, off);
                        if (ov < v) v = ov;
                    }
                    if (v < bestv[a]) bestv[a] = v;
                }
#pragma unroll
            for (int mt = 0; mt < 2; mt++)
#pragma unroll
                for (int nt = 0; nt < 8; nt++)
#pragma unroll
                    for (int r = 0; r < 4; r++) acc[mt][nt][r] = 0.f;

            __syncthreads();
            // cooperative store staging -> g_s (fp16)
#pragma unroll
            for (int i = 0; i < 8; i++) {
                int idx = tid + i * 256;
                int row = idx >> 4;
                int c8  = idx & 15;
                float4 v4 = *(const float4*)&stage[row * STROW_H + c8 * 8];
                *(float4*)&g_s[(size_t)(brow + row) * K + kt + c8 * 8] = v4;
            }
        }
    }

    // merge the two warpN halves -> per-row min
    __syncthreads();
    float* sv = (float*)(smem + STAGE_OFF_H);
    if (t == 0) {
#pragma unroll
        for (int a = 0; a < 4; a++) {
            int row = warpM * 32 + (a >> 1) * 16 + (a & 1) * 8 + g;
            sv[warpN * 128 + row] = bestv[a];
        }
    }
    __syncthreads();
    if (tid < BM) {
        float v0 = sv[tid], v1 = sv[128 + tid];
        g_rmin[brow + tid] = (v1 < v0) ? v1 : v0;
    }
}

// ---- Phase 2: per-row scan + compact + exact rescue ----------------------
// One 128-thread block per row.
__global__ __launch_bounds__(128)
void scan_rescue_kernel(const float* __restrict__ z,
                        const float* __restrict__ emb, int K)
{
    __shared__ int   sCand[CAP];
    __shared__ int   sCnt;
    __shared__ float sv[128];
    __shared__ int   si[128];

    const int row = blockIdx.x;
    const int tid = threadIdx.x;

    if (tid == 0) sCnt = 0;
    __syncthreads();

    const float thresh = g_rmin[row] + MARGIN;
    const uint4* srow = (const uint4*)(g_s + (size_t)row * K);   // K/8 uint4

    // coalesced scan, compact hits to smem
    for (int j = 0; j < K / (128 * 8); j++) {
        int u4i = tid + j * 128;
        uint4 u = srow[u4i];
        unsigned uw[4] = {u.x, u.y, u.z, u.w};
#pragma unroll
        for (int p = 0; p < 4; p++) {
            float2 f = __half22float2(*reinterpret_cast<const __half2*>(&uw[p]));
            if (f.x <= thresh) {
                int pos = atomicAdd(&sCnt, 1);
                if (pos < CAP) sCand[pos] = u4i * 8 + p * 2;
            }
            if (f.y <= thresh) {
                int pos = atomicAdd(&sCnt, 1);
                if (pos < CAP) sCand[pos] = u4i * 8 + p * 2 + 1;
            }
        }
    }
    __syncthreads();
    const int cnt = sCnt;

    const float zz   = g_zz[row];
    const float4* zp = (const float4*)(z + (size_t)row * DDIM);

    float v  = 3.4e38f;
    int   bi = 0x7FFFFFFF;

    if (cnt <= CAP) {
        for (int ci = tid; ci < cnt; ci += 128) {
            int k = sCand[ci];
            const float4* ep = (const float4*)(emb + (size_t)k * DDIM);
            float accd = 0.f;
#pragma unroll 4
            for (int d = 0; d < DDIM / 4; d++) {
                float4 za = zp[d], ea = ep[d];
                accd = fmaf(za.x, ea.x, accd);
                accd = fmaf(za.y, ea.y, accd);
                accd = fmaf(za.z, ea.z, accd);
                accd = fmaf(za.w, ea.w, accd);
            }
            float q = fmaf(-2.f, accd, zz) + g_ee[k];
            if (q < v || (q == v && k < bi)) { v = q; bi = k; }
        }
    } else {
        // overflow fallback: exact scan over all k (statistically unreachable)
        for (int k = tid; k < K; k += 128) {
            const float4* ep = (const float4*)(emb + (size_t)k * DDIM);
            float accd = 0.f;
#pragma unroll 4
            for (int d = 0; d < DDIM / 4; d++) {
                float4 za = zp[d], ea = ep[d];
                accd = fmaf(za.x, ea.x, accd);
                accd = fmaf(za.y, ea.y, accd);
                accd = fmaf(za.z, ea.z, accd);
                accd = fmaf(za.w, ea.w, accd);
            }
            float q = fmaf(-2.f, accd, zz) + g_ee[k];
            if (q < v || (q == v && k < bi)) { v = q; bi = k; }
        }
    }

    sv[tid] = v;
    si[tid] = bi;
    __syncthreads();
#pragma unroll
    for (int s = 64; s > 0; s >>= 1) {
        if (tid < s) {
            float ov = sv[tid + s];
            int   oi = si[tid + s];
            if (ov < sv[tid] || (ov == sv[tid] && oi < si[tid])) {
                sv[tid] = ov; si[tid] = oi;
            }
        }
        __syncthreads();
    }
    if (tid == 0) g_best[row] = si[0];
}

// ---- output + loss -------------------------------------------------------
__global__ void gather_loss_kernel(const float* __restrict__ z,
                                   const float* __restrict__ emb,
                                   float* __restrict__ out_zq,
                                   float* __restrict__ out_idx,
                                   int B)
{
    __shared__ double sred[128];
    const int tid = threadIdx.x;
    double lsum = 0.0;

    for (int r = 0; r < 32; r++) {
        int b   = blockIdx.x * 32 + r;
        int idx = g_best[b];
        if (tid == 0 && out_idx) out_idx[b] = (float)idx;

        float4 zv = ((const float4*)(z   + (size_t)b   * DDIM))[tid];
        float4 ev = ((const float4*)(emb + (size_t)idx * DDIM))[tid];
        float4 o;
        float dx;
        dx = ev.x - zv.x; o.x = zv.x + dx; lsum += (double)dx * (double)dx;
        dx = ev.y - zv.y; o.y = zv.y + dx; lsum += (double)dx * (double)dx;
        dx = ev.z - zv.z; o.z = zv.z + dx; lsum += (double)dx * (double)dx;
        dx = ev.w - zv.w; o.w = zv.w + dx; lsum += (double)dx * (double)dx;
        ((float4*)(out_zq + (size_t)b * DDIM))[tid] = o;
    }

    sred[tid] = lsum;
    __syncthreads();
#pragma unroll
    for (int s = 64; s > 0; s >>= 1) {
        if (tid < s) sred[tid] += sred[tid + s];
        __syncthreads();
    }
    if (tid == 0) g_part[blockIdx.x] = sred[0];
}

__global__ void finalize_kernel(float* __restrict__ out_loss, int nparts, double scale)
{
    double s = 0.0;
    for (int i = 0; i < nparts; i++) s += g_part[i];
    *out_loss = (float)(s * scale);
}

// -------------------------------------------------------------------------
extern "C" void kernel_launch(void* const* d_in, const int* in_sizes, int n_in,
                              void* d_out, int out_size)
{
    const float* z   = (const float*)d_in[0];
    const float* emb = (const float*)d_in[1];
    int B = in_sizes[0] / DDIM;   // 16384
    int K = in_sizes[1] / DDIM;   // 8192

    float* out      = (float*)d_out;
    float* out_zq   = out;
    float* out_idx  = ((size_t)out_size >= (size_t)B * DDIM + (size_t)B)
                        ? out + (size_t)B * DDIM : nullptr;
    float* out_loss = ((size_t)out_size >= (size_t)B * DDIM + (size_t)B + 1)
                        ? out + (size_t)B * DDIM + B : nullptr;

    __nv_bfloat16 *zb, *eb;
    cudaGetSymbolAddress((void**)&zb, g_zb);
    cudaGetSymbolAddress((void**)&eb, g_eb);

    static int smem_set = 0;
    const int dyn_smem = (2 * BUF_H + 128 * STROW_H) * 2;   // 75776 B
    if (!smem_set) {
        cudaFuncSetAttribute(vq_phase1_kernel,
                             cudaFuncAttributeMaxDynamicSharedMemorySize, dyn_smem);
        smem_set = 1;
    }

    int nz4 = B * DDIM / 4, ne4 = K * DDIM / 4;
    to_bf16_kernel<<<(nz4 + 255) / 256, 256>>>(z, zb, nz4);
    to_bf16_kernel<<<(ne4 + 255) / 256, 256>>>(emb, eb, ne4);
    rowsq_kernel<<<((K + B) * 32 + 255) / 256, 256>>>(emb, z, K, B);

    vq_phase1_kernel<<<B / BM, 256, dyn_smem>>>(K);
    scan_rescue_kernel<<<B, 128>>>(z, emb, K);

    int gblocks = B / 32;
    gather_loss_kernel<<<gblocks, 128>>>(z, emb, out_zq, out_idx, B);
    if (out_loss)
        finalize_kernel<<<1, 1>>>(out_loss, gblocks, 1.25 / ((double)B * (double)DDIM));
}

// round 9
// speedup vs baseline: 5.3474x; 1.0017x over previous
#include <cuda_runtime.h>
#include <cuda_bf16.h>
#include <cuda_fp16.h>
#include <cstdint>
#include <cstddef>

// VectorQuantizer, two-phase:
//   Phase 1: bf16 ldmatrix+mma GEMM (512 thr, 16 warps, warp tile 32x32) ->
//            fp16 screen s[b,k] = ee - 2*G (256 MB) + per-row fp32 min.
//   Phase 2: per-row scan of the screen (final-min + MARGIN) -> compact
//            candidates -> exact fp32 rescue (bit-identical Round-2 chain).
// Output: [ z_q_st (B*512) | indices as float (B) | vq_loss (1) ]

#define DDIM 512
#define NB 16384
#define NK 8192
#define BM 128
#define BN 128

#define SA 40                    // smem row stride in halves (80B, LDSM conflict-free)
#define ABUF_H (128 * SA)
#define BUF_H  (2 * ABUF_H)
#define STAGE_OFF_H (2 * BUF_H)
#define STROW_H 136

#define CAP 64
#define MARGIN 2e-3f

__device__ float  g_ee[NK];
__device__ float  g_zz[NB];
__device__ float  g_rmin[NB];
__device__ int    g_best[NB];
__device__ double g_part[512];

__device__ __nv_bfloat16 g_zb[NB * DDIM];
__device__ __nv_bfloat16 g_eb[NK * DDIM];
__device__ __half        g_s[(size_t)NB * NK];  // fp16 screen, 256 MB

// ---- helpers -------------------------------------------------------------
__device__ __forceinline__ unsigned smem_u32(const void* p)
{
    return (unsigned)__cvta_generic_to_shared(p);
}
__device__ __forceinline__ void cp16(__half* sdst, const void* gsrc)
{
    asm volatile("cp.async.ca.shared.global [%0], [%1], 16;\n"
                 :: "r"(smem_u32(sdst)), "l"(gsrc));
}
__device__ __forceinline__ void cp_commit() { asm volatile("cp.async.commit_group;\n"); }
__device__ __forceinline__ void cp_wait0()  { asm volatile("cp.async.wait_group 0;\n"); }

__device__ __forceinline__ void ldsm4(unsigned* r, unsigned addr)
{
    asm volatile("ldmatrix.sync.aligned.m8n8.x4.shared.b16 {%0,%1,%2,%3}, [%4];"
                 : "=r"(r[0]), "=r"(r[1]), "=r"(r[2]), "=r"(r[3]) : "r"(addr));
}
__device__ __forceinline__ void mma_bf16(float* c, const unsigned* a,
                                         unsigned b0, unsigned b1)
{
    asm volatile(
        "mma.sync.aligned.m16n8k16.row.col.f32.bf16.bf16.f32 "
        "{%0,%1,%2,%3}, {%4,%5,%6,%7}, {%8,%9}, {%0,%1,%2,%3};\n"
        : "+f"(c[0]), "+f"(c[1]), "+f"(c[2]), "+f"(c[3])
        : "r"(a[0]), "r"(a[1]), "r"(a[2]), "r"(a[3]), "r"(b0), "r"(b1));
}

// ---- prep ----------------------------------------------------------------
__global__ void to_bf16_kernel(const float* __restrict__ src,
                               __nv_bfloat16* __restrict__ dst, int n4)
{
    int i = blockIdx.x * blockDim.x + threadIdx.x;
    if (i >= n4) return;
    float4 v = ((const float4*)src)[i];
    __nv_bfloat162 p0 = __floats2bfloat162_rn(v.x, v.y);
    __nv_bfloat162 p1 = __floats2bfloat162_rn(v.z, v.w);
    uint2 w;
    w.x = *reinterpret_cast<unsigned*>(&p0);
    w.y = *reinterpret_cast<unsigned*>(&p1);
    ((uint2*)dst)[i] = w;
}

__global__ void rowsq_kernel(const float* __restrict__ emb,
                             const float* __restrict__ z,
                             int K, int B)
{
    int w    = (blockIdx.x * blockDim.x + threadIdx.x) >> 5;
    int lane = threadIdx.x & 31;
    if (w >= K + B) return;
    const float* src = (w < K) ? (emb + (size_t)w * DDIM)
                               : (z   + (size_t)(w - K) * DDIM);
    float s = 0.f;
#pragma unroll
    for (int t = 0; t < DDIM / 32; t++) {
        float x = src[lane + 32 * t];
        s = fmaf(x, x, s);
    }
#pragma unroll
    for (int off = 16; off > 0; off >>= 1)
        s += __shfl_xor_sync(0xFFFFFFFFu, s, off);
    if (lane == 0) {
        if (w < K) g_ee[w] = s;
        else       g_zz[w - K] = s;
    }
}

// ---- Phase 1: 512 threads = 16 warps (4 warpM x 4 warpN), warp tile 32x32
__global__ __launch_bounds__(512, 1)
void vq_phase1_kernel(int K)
{
    extern __shared__ __half smem[];
    __shared__ float sEE[BN];

    const int tid   = threadIdx.x;
    const int wid   = tid >> 5;
    const int lane  = tid & 31;
    const int g     = lane >> 2;
    const int t     = lane & 3;
    const int warpM = wid >> 2;      // 0..3
    const int warpN = wid & 3;       // 0..3
    const int brow  = blockIdx.x * BM;

    float bestv[4];
#pragma unroll
    for (int a = 0; a < 4; a++) bestv[a] = 3.4e38f;

    // cp.async mapping: per operand 128 rows x 4 chunks of 16B; 1 per thread
    const int cr = tid >> 2;
    const int cc = (tid & 3) * 8;

    // ldmatrix lane offsets (validated R6/R7)
    const int aRow = lane & 15;
    const int aCol = (lane >> 4) << 3;
    const int bRow = (lane & 7) + ((lane & 16) >> 1);
    const int bCol = lane & 8;

    const int NCH = (K / BN) * (DDIM / 32);   // 1024

    // prologue: chunk 0 -> buffer 0
    {
        __half* bA = smem;
        __half* bB = smem + ABUF_H;
        cp16(bA + cr * SA + cc, g_zb + (size_t)(brow + cr) * DDIM + cc);
        cp16(bB + cr * SA + cc, g_eb + (size_t)cr * DDIM + cc);
        cp_commit();
    }

    float acc[2][4][4];
#pragma unroll
    for (int mt = 0; mt < 2; mt++)
#pragma unroll
        for (int nt = 0; nt < 4; nt++)
#pragma unroll
            for (int r = 0; r < 4; r++) acc[mt][nt][r] = 0.f;

    for (int c = 0; c < NCH; c++) {
        const int dch = c & 15;
        const int kt  = (c >> 4) * BN;
        __half* bA = smem + (c & 1) * BUF_H;
        __half* bB = bA + ABUF_H;

        cp_wait0();
        __syncthreads();

        if (dch == 0 && tid < BN) sEE[tid] = g_ee[kt + tid];

        if (c + 1 < NCH) {
            const int ndb = ((c + 1) & 15) * 32;
            const int nkt = ((c + 1) >> 4) * BN;
            __half* nA = smem + ((c + 1) & 1) * BUF_H;
            __half* nB = nA + ABUF_H;
            cp16(nA + cr * SA + cc, g_zb + (size_t)(brow + cr) * DDIM + ndb + cc);
            cp16(nB + cr * SA + cc, g_eb + (size_t)(nkt + cr) * DDIM + ndb + cc);
            cp_commit();
        }

        // compute: 2 k16 steps, ldmatrix feeds
#pragma unroll
        for (int ks = 0; ks < 2; ks++) {
            const int kb = ks * 16;
            unsigned A[2][4], Bf[2][4];
#pragma unroll
            for (int mt = 0; mt < 2; mt++)
                ldsm4(A[mt], smem_u32(&bA[(warpM * 32 + mt * 16 + aRow) * SA + kb + aCol]));
#pragma unroll
            for (int np = 0; np < 2; np++)
                ldsm4(Bf[np], smem_u32(&bB[(warpN * 32 + np * 16 + bRow) * SA + kb + bCol]));
#pragma unroll
            for (int mt = 0; mt < 2; mt++)
#pragma unroll
                for (int nt = 0; nt < 4; nt++)
                    mma_bf16(acc[mt][nt], A[mt],
                             Bf[nt >> 1][(nt & 1) * 2], Bf[nt >> 1][(nt & 1) * 2 + 1]);
        }

        if (dch == 15) {
            __half* stage = smem + STAGE_OFF_H;
#pragma unroll
            for (int mt = 0; mt < 2; mt++)
#pragma unroll
                for (int i = 0; i < 2; i++) {
                    const int a = mt * 2 + i;
                    const int srow = warpM * 32 + mt * 16 + i * 8 + g;
                    float v = 3.4e38f;
#pragma unroll
                    for (int nt = 0; nt < 4; nt++) {
                        int col = warpN * 32 + nt * 8 + 2 * t;
                        float s0 = fmaf(-2.f, acc[mt][nt][i * 2 + 0], sEE[col]);
                        float s1 = fmaf(-2.f, acc[mt][nt][i * 2 + 1], sEE[col + 1]);
                        *(__half2*)&stage[srow * STROW_H + col] =
                            __floats2half2_rn(s0, s1);
                        float m = (s0 < s1) ? s0 : s1;
                        if (m < v) v = m;
                    }
#pragma unroll
                    for (int off = 1; off < 4; off <<= 1) {
                        float ov = __shfl_xor_sync(0xFFFFFFFFu, v, off);
                        if (ov < v) v = ov;
                    }
                    if (v < bestv[a]) bestv[a] = v;
                }
#pragma unroll
            for (int mt = 0; mt < 2; mt++)
#pragma unroll
                for (int nt = 0; nt < 4; nt++)
#pragma unroll
                    for (int r = 0; r < 4; r++) acc[mt][nt][r] = 0.f;

            __syncthreads();
            // cooperative store staging -> g_s (fp16): 2048 float4s, 4/thread
#pragma unroll
            for (int i = 0; i < 4; i++) {
                int idx = tid + i * 512;
                int row = idx >> 4;
                int c8  = idx & 15;
                float4 v4 = *(const float4*)&stage[row * STROW_H + c8 * 8];
                *(float4*)&g_s[(size_t)(brow + row) * K + kt + c8 * 8] = v4;
            }
        }
    }

    // merge the four warpN quarters -> per-row min
    __syncthreads();
    float* sv = (float*)(smem + STAGE_OFF_H);   // [4][128]
    if (t == 0) {
#pragma unroll
        for (int a = 0; a < 4; a++) {
            int row = warpM * 32 + (a >> 1) * 16 + (a & 1) * 8 + g;
            sv[warpN * 128 + row] = bestv[a];
        }
    }
    __syncthreads();
    if (tid < BM) {
        float v0 = sv[tid];
        float v1 = sv[128 + tid];
        float v2 = sv[256 + tid];
        float v3 = sv[384 + tid];
        float m01 = (v1 < v0) ? v1 : v0;
        float m23 = (v3 < v2) ? v3 : v2;
        g_rmin[brow + tid] = (m23 < m01) ? m23 : m01;
    }
}

// ---- Phase 2: per-row scan + compact + exact rescue ----------------------
__global__ __launch_bounds__(128)
void scan_rescue_kernel(const float* __restrict__ z,
                        const float* __restrict__ emb, int K)
{
    __shared__ int   sCand[CAP];
    __shared__ int   sCnt;
    __shared__ float sv[128];
    __shared__ int   si[128];

    const int row = blockIdx.x;
    const int tid = threadIdx.x;

    if (tid == 0) sCnt = 0;
    __syncthreads();

    const float thresh = g_rmin[row] + MARGIN;
    const uint4* srow = (const uint4*)(g_s + (size_t)row * K);

    for (int j = 0; j < K / (128 * 8); j++) {
        int u4i = tid + j * 128;
        uint4 u = srow[u4i];
        unsigned uw[4] = {u.x, u.y, u.z, u.w};
#pragma unroll
        for (int p = 0; p < 4; p++) {
            float2 f = __half22float2(*reinterpret_cast<const __half2*>(&uw[p]));
            if (f.x <= thresh) {
                int pos = atomicAdd(&sCnt, 1);
                if (pos < CAP) sCand[pos] = u4i * 8 + p * 2;
            }
            if (f.y <= thresh) {
                int pos = atomicAdd(&sCnt, 1);
                if (pos < CAP) sCand[pos] = u4i * 8 + p * 2 + 1;
            }
        }
    }
    __syncthreads();
    const int cnt = sCnt;

    const float zz   = g_zz[row];
    const float4* zp = (const float4*)(z + (size_t)row * DDIM);

    float v  = 3.4e38f;
    int   bi = 0x7FFFFFFF;

    if (cnt <= CAP) {
        for (int ci = tid; ci < cnt; ci += 128) {
            int k = sCand[ci];
            const float4* ep = (const float4*)(emb + (size_t)k * DDIM);
            float accd = 0.f;
#pragma unroll 4
            for (int d = 0; d < DDIM / 4; d++) {
                float4 za = zp[d], ea = ep[d];
                accd = fmaf(za.x, ea.x, accd);
                accd = fmaf(za.y, ea.y, accd);
                accd = fmaf(za.z, ea.z, accd);
                accd = fmaf(za.w, ea.w, accd);
            }
            float q = fmaf(-2.f, accd, zz) + g_ee[k];
            if (q < v || (q == v && k < bi)) { v = q; bi = k; }
        }
    } else {
        for (int k = tid; k < K; k += 128) {
            const float4* ep = (const float4*)(emb + (size_t)k * DDIM);
            float accd = 0.f;
#pragma unroll 4
            for (int d = 0; d < DDIM / 4; d++) {
                float4 za = zp[d], ea = ep[d];
                accd = fmaf(za.x, ea.x, accd);
                accd = fmaf(za.y, ea.y, accd);
                accd = fmaf(za.z, ea.z, accd);
                accd = fmaf(za.w, ea.w, accd);
            }
            float q = fmaf(-2.f, accd, zz) + g_ee[k];
            if (q < v || (q == v && k < bi)) { v = q; bi = k; }
        }
    }

    sv[tid] = v;
    si[tid] = bi;
    __syncthreads();
#pragma unroll
    for (int s = 64; s > 0; s >>= 1) {
        if (tid < s) {
            float ov = sv[tid + s];
            int   oi = si[tid + s];
            if (ov < sv[tid] || (ov == sv[tid] && oi < si[tid])) {
                sv[tid] = ov; si[tid] = oi;
            }
        }
        __syncthreads();
    }
    if (tid == 0) g_best[row] = si[0];
}

// ---- output + loss -------------------------------------------------------
__global__ void gather_loss_kernel(const float* __restrict__ z,
                                   const float* __restrict__ emb,
                                   float* __restrict__ out_zq,
                                   float* __restrict__ out_idx,
                                   int B)
{
    __shared__ double sred[128];
    const int tid = threadIdx.x;
    double lsum = 0.0;

    for (int r = 0; r < 32; r++) {
        int b   = blockIdx.x * 32 + r;
        int idx = g_best[b];
        if (tid == 0 && out_idx) out_idx[b] = (float)idx;

        float4 zv = ((const float4*)(z   + (size_t)b   * DDIM))[tid];
        float4 ev = ((const float4*)(emb + (size_t)idx * DDIM))[tid];
        float4 o;
        float dx;
        dx = ev.x - zv.x; o.x = zv.x + dx; lsum += (double)dx * (double)dx;
        dx = ev.y - zv.y; o.y = zv.y + dx; lsum += (double)dx * (double)dx;
        dx = ev.z - zv.z; o.z = zv.z + dx; lsum += (double)dx * (double)dx;
        dx = ev.w - zv.w; o.w = zv.w + dx; lsum += (double)dx * (double)dx;
        ((float4*)(out_zq + (size_t)b * DDIM))[tid] = o;
    }

    sred[tid] = lsum;
    __syncthreads();
#pragma unroll
    for (int s = 64; s > 0; s >>= 1) {
        if (tid < s) sred[tid] += sred[tid + s];
        __syncthreads();
    }
    if (tid == 0) g_part[blockIdx.x] = sred[0];
}

__global__ void finalize_kernel(float* __restrict__ out_loss, int nparts, double scale)
{
    __shared__ double sred[512];
    int tid = threadIdx.x;
    sred[tid] = (tid < nparts) ? g_part[tid] : 0.0;
    __syncthreads();
#pragma unroll
    for (int s = 256; s > 0; s >>= 1) {
        if (tid < s) sred[tid] += sred[tid + s];
        __syncthreads();
    }
    if (tid == 0) *out_loss = (float)(sred[0] * scale);
}

// -------------------------------------------------------------------------
extern "C" void kernel_launch(void* const* d_in, const int* in_sizes, int n_in,
                              void* d_out, int out_size)
{
    const float* z   = (const float*)d_in[0];
    const float* emb = (const float*)d_in[1];
    int B = in_sizes[0] / DDIM;   // 16384
    int K = in_sizes[1] / DDIM;   // 8192

    float* out      = (float*)d_out;
    float* out_zq   = out;
    float* out_idx  = ((size_t)out_size >= (size_t)B * DDIM + (size_t)B)
                        ? out + (size_t)B * DDIM : nullptr;
    float* out_loss = ((size_t)out_size >= (size_t)B * DDIM + (size_t)B + 1)
                        ? out + (size_t)B * DDIM + B : nullptr;

    __nv_bfloat16 *zb, *eb;
    cudaGetSymbolAddress((void**)&zb, g_zb);
    cudaGetSymbolAddress((void**)&eb, g_eb);

    static int smem_set = 0;
    const int dyn_smem = (2 * BUF_H + 128 * STROW_H) * 2;   // 75776 B
    if (!smem_set) {
        cudaFuncSetAttribute(vq_phase1_kernel,
                             cudaFuncAttributeMaxDynamicSharedMemorySize, dyn_smem);
        smem_set = 1;
    }

    int nz4 = B * DDIM / 4, ne4 = K * DDIM / 4;
    to_bf16_kernel<<<(nz4 + 255) / 256, 256>>>(z, zb, nz4);
    to_bf16_kernel<<<(ne4 + 255) / 256, 256>>>(emb, eb, ne4);
    rowsq_kernel<<<((K + B) * 32 + 255) / 256, 256>>>(emb, z, K, B);

    vq_phase1_kernel<<<B / BM, 512, dyn_smem>>>(K);
    scan_rescue_kernel<<<B, 128>>>(z, emb, K);

    int gblocks = B / 32;
    gather_loss_kernel<<<gblocks, 128>>>(z, emb, out_zq, out_idx, B);
    if (out_loss)
        finalize_kernel<<<1, 512>>>(out_loss, gblocks, 1.25 / ((double)B * (double)DDIM));
}

// round 10
// speedup vs baseline: 6.0213x; 1.1260x over previous
#include <cuda_runtime.h>
#include <cuda_bf16.h>
#include <cuda_fp16.h>
#include <cstdint>
#include <cstddef>

// VectorQuantizer, two-phase:
//   Phase 1: bf16 ldmatrix+mma GEMM, BM=64 tiles, 2 CTAs/SM co-resident ->
//            fp16 screen s[b,k] = ee - 2*G (256 MB) + per-row fp32 min.
//   Phase 2: per-row scan of the screen (final-min + MARGIN) -> compact
//            candidates -> exact fp32 rescue (bit-identical Round-2 chain).
// Output: [ z_q_st (B*512) | indices as float (B) | vq_loss (1) ]

#define DDIM 512
#define NB 16384
#define NK 8192
#define BM 64
#define BN 128

#define SA 40                      // smem row stride in halves (80B, LDSM conflict-free)
#define ABUF_H (64 * SA)           // A tile: 64 rows
#define BBUF_H (128 * SA)          // B tile: 128 rows
#define BUF_H  (ABUF_H + BBUF_H)   // 7680 halves per pipeline buffer
#define STAGE_OFF_H (2 * BUF_H)    // 15360
#define STROW_H 136

#define CAP 64
#define MARGIN 2e-3f

__device__ float  g_ee[NK];
__device__ float  g_zz[NB];
__device__ float  g_rmin[NB];
__device__ int    g_best[NB];
__device__ double g_part[512];

__device__ __nv_bfloat16 g_zb[NB * DDIM];
__device__ __nv_bfloat16 g_eb[NK * DDIM];
__device__ __half        g_s[(size_t)NB * NK];  // fp16 screen, 256 MB

// ---- helpers -------------------------------------------------------------
__device__ __forceinline__ unsigned smem_u32(const void* p)
{
    return (unsigned)__cvta_generic_to_shared(p);
}
__device__ __forceinline__ void cp16(__half* sdst, const void* gsrc)
{
    asm volatile("cp.async.ca.shared.global [%0], [%1], 16;\n"
                 :: "r"(smem_u32(sdst)), "l"(gsrc));
}
__device__ __forceinline__ void cp_commit() { asm volatile("cp.async.commit_group;\n"); }
__device__ __forceinline__ void cp_wait0()  { asm volatile("cp.async.wait_group 0;\n"); }

__device__ __forceinline__ void ldsm4(unsigned* r, unsigned addr)
{
    asm volatile("ldmatrix.sync.aligned.m8n8.x4.shared.b16 {%0,%1,%2,%3}, [%4];"
                 : "=r"(r[0]), "=r"(r[1]), "=r"(r[2]), "=r"(r[3]) : "r"(addr));
}
__device__ __forceinline__ void mma_bf16(float* c, const unsigned* a,
                                         unsigned b0, unsigned b1)
{
    asm volatile(
        "mma.sync.aligned.m16n8k16.row.col.f32.bf16.bf16.f32 "
        "{%0,%1,%2,%3}, {%4,%5,%6,%7}, {%8,%9}, {%0,%1,%2,%3};\n"
        : "+f"(c[0]), "+f"(c[1]), "+f"(c[2]), "+f"(c[3])
        : "r"(a[0]), "r"(a[1]), "r"(a[2]), "r"(a[3]), "r"(b0), "r"(b1));
}

// ---- prep ----------------------------------------------------------------
__global__ void to_bf16_kernel(const float* __restrict__ src,
                               __nv_bfloat16* __restrict__ dst, int n4)
{
    int i = blockIdx.x * blockDim.x + threadIdx.x;
    if (i >= n4) return;
    float4 v = ((const float4*)src)[i];
    __nv_bfloat162 p0 = __floats2bfloat162_rn(v.x, v.y);
    __nv_bfloat162 p1 = __floats2bfloat162_rn(v.z, v.w);
    uint2 w;
    w.x = *reinterpret_cast<unsigned*>(&p0);
    w.y = *reinterpret_cast<unsigned*>(&p1);
    ((uint2*)dst)[i] = w;
}

__global__ void rowsq_kernel(const float* __restrict__ emb,
                             const float* __restrict__ z,
                             int K, int B)
{
    int w    = (blockIdx.x * blockDim.x + threadIdx.x) >> 5;
    int lane = threadIdx.x & 31;
    if (w >= K + B) return;
    const float* src = (w < K) ? (emb + (size_t)w * DDIM)
                               : (z   + (size_t)(w - K) * DDIM);
    float s = 0.f;
#pragma unroll
    for (int t = 0; t < DDIM / 32; t++) {
        float x = src[lane + 32 * t];
        s = fmaf(x, x, s);
    }
#pragma unroll
    for (int off = 16; off > 0; off >>= 1)
        s += __shfl_xor_sync(0xFFFFFFFFu, s, off);
    if (lane == 0) {
        if (w < K) g_ee[w] = s;
        else       g_zz[w - K] = s;
    }
}

// ---- Phase 1: BM=64 tiles, 256 thr, 8 warps (2 warpM x 4 warpN), 2 CTAs/SM
__global__ __launch_bounds__(256, 2)
void vq_phase1_kernel(int K)
{
    extern __shared__ __half smem[];
    __shared__ float sEE[BN];

    const int tid   = threadIdx.x;
    const int wid   = tid >> 5;
    const int lane  = tid & 31;
    const int g     = lane >> 2;
    const int t     = lane & 3;
    const int warpM = wid >> 2;      // 0..1
    const int warpN = wid & 3;       // 0..3
    const int brow  = blockIdx.x * BM;

    float bestv[4];
#pragma unroll
    for (int a = 0; a < 4; a++) bestv[a] = 3.4e38f;

    // cp.async mapping
    const int acr = tid >> 2;          // A: 64 rows x 4 x 16B = 256 units, 1/thread
    const int acc_ = (tid & 3) * 8;
    int bcr[2], bcc[2];                // B: 128 rows x 4 x 16B = 512 units, 2/thread
#pragma unroll
    for (int i = 0; i < 2; i++) {
        int idx = tid + i * 256;
        bcr[i] = idx >> 2;
        bcc[i] = (idx & 3) * 8;
    }

    // ldmatrix lane offsets (validated R6/R7/R9)
    const int aRow = lane & 15;
    const int aCol = (lane >> 4) << 3;
    const int bRow = (lane & 7) + ((lane & 16) >> 1);
    const int bCol = lane & 8;

    const int NCH = (K / BN) * (DDIM / 32);   // 1024

    // prologue: chunk 0 -> buffer 0
    {
        __half* bA = smem;
        __half* bB = smem + ABUF_H;
        cp16(bA + acr * SA + acc_, g_zb + (size_t)(brow + acr) * DDIM + acc_);
#pragma unroll
        for (int i = 0; i < 2; i++)
            cp16(bB + bcr[i] * SA + bcc[i], g_eb + (size_t)bcr[i] * DDIM + bcc[i]);
        cp_commit();
    }

    float acc[2][4][4];
#pragma unroll
    for (int mt = 0; mt < 2; mt++)
#pragma unroll
        for (int nt = 0; nt < 4; nt++)
#pragma unroll
            for (int r = 0; r < 4; r++) acc[mt][nt][r] = 0.f;

    for (int c = 0; c < NCH; c++) {
        const int dch = c & 15;
        const int kt  = (c >> 4) * BN;
        __half* bA = smem + (c & 1) * BUF_H;
        __half* bB = bA + ABUF_H;

        cp_wait0();
        __syncthreads();

        if (dch == 0 && tid < BN) sEE[tid] = g_ee[kt + tid];

        if (c + 1 < NCH) {
            const int ndb = ((c + 1) & 15) * 32;
            const int nkt = ((c + 1) >> 4) * BN;
            __half* nA = smem + ((c + 1) & 1) * BUF_H;
            __half* nB = nA + ABUF_H;
            cp16(nA + acr * SA + acc_, g_zb + (size_t)(brow + acr) * DDIM + ndb + acc_);
#pragma unroll
            for (int i = 0; i < 2; i++)
                cp16(nB + bcr[i] * SA + bcc[i],
                     g_eb + (size_t)(nkt + bcr[i]) * DDIM + ndb + bcc[i]);
            cp_commit();
        }

        // compute: 2 k16 steps, ldmatrix feeds
#pragma unroll
        for (int ks = 0; ks < 2; ks++) {
            const int kb = ks * 16;
            unsigned A[2][4], Bf[2][4];
#pragma unroll
            for (int mt = 0; mt < 2; mt++)
                ldsm4(A[mt], smem_u32(&bA[(warpM * 32 + mt * 16 + aRow) * SA + kb + aCol]));
#pragma unroll
            for (int np = 0; np < 2; np++)
                ldsm4(Bf[np], smem_u32(&bB[(warpN * 32 + np * 16 + bRow) * SA + kb + bCol]));
#pragma unroll
            for (int mt = 0; mt < 2; mt++)
#pragma unroll
                for (int nt = 0; nt < 4; nt++)
                    mma_bf16(acc[mt][nt], A[mt],
                             Bf[nt >> 1][(nt & 1) * 2], Bf[nt >> 1][(nt & 1) * 2 + 1]);
        }

        if (dch == 15) {
            __half* stage = smem + STAGE_OFF_H;
#pragma unroll
            for (int mt = 0; mt < 2; mt++)
#pragma unroll
                for (int i = 0; i < 2; i++) {
                    const int a = mt * 2 + i;
                    const int srow = warpM * 32 + mt * 16 + i * 8 + g;
                    float v = 3.4e38f;
#pragma unroll
                    for (int nt = 0; nt < 4; nt++) {
                        int col = warpN * 32 + nt * 8 + 2 * t;
                        float s0 = fmaf(-2.f, acc[mt][nt][i * 2 + 0], sEE[col]);
                        float s1 = fmaf(-2.f, acc[mt][nt][i * 2 + 1], sEE[col + 1]);
                        *(__half2*)&stage[srow * STROW_H + col] =
                            __floats2half2_rn(s0, s1);
                        float m = (s0 < s1) ? s0 : s1;
                        if (m < v) v = m;
                    }
#pragma unroll
                    for (int off = 1; off < 4; off <<= 1) {
                        float ov = __shfl_xor_sync(0xFFFFFFFFu, v, off);
                        if (ov < v) v = ov;
                    }
                    if (v < bestv[a]) bestv[a] = v;
                }
#pragma unroll
            for (int mt = 0; mt < 2; mt++)
#pragma unroll
                for (int nt = 0; nt < 4; nt++)
#pragma unroll
                    for (int r = 0; r < 4; r++) acc[mt][nt][r] = 0.f;

            __syncthreads();
            // cooperative store staging -> g_s (fp16): 64 rows x 16 float4 = 1024
#pragma unroll
            for (int i = 0; i < 4; i++) {
                int idx = tid + i * 256;
                int row = idx >> 4;
                int c8  = idx & 15;
                float4 v4 = *(const float4*)&stage[row * STROW_H + c8 * 8];
                *(float4*)&g_s[(size_t)(brow + row) * K + kt + c8 * 8] = v4;
            }
        }
    }

    // merge the four warpN quarters -> per-row min
    __syncthreads();
    float* sv = (float*)(smem + STAGE_OFF_H);   // [4][64]
    if (t == 0) {
#pragma unroll
        for (int a = 0; a < 4; a++) {
            int row = warpM * 32 + (a >> 1) * 16 + (a & 1) * 8 + g;
            sv[warpN * 64 + row] = bestv[a];
        }
    }
    __syncthreads();
    if (tid < BM) {
        float v0 = sv[tid];
        float v1 = sv[64 + tid];
        float v2 = sv[128 + tid];
        float v3 = sv[192 + tid];
        float m01 = (v1 < v0) ? v1 : v0;
        float m23 = (v3 < v2) ? v3 : v2;
        g_rmin[brow + tid] = (m23 < m01) ? m23 : m01;
    }
}

// ---- Phase 2: per-row scan + compact + exact rescue ----------------------
__global__ __launch_bounds__(128)
void scan_rescue_kernel(const float* __restrict__ z,
                        const float* __restrict__ emb, int K)
{
    __shared__ int   sCand[CAP];
    __shared__ int   sCnt;
    __shared__ float sv[128];
    __shared__ int   si[128];

    const int row = blockIdx.x;
    const int tid = threadIdx.x;

    if (tid == 0) sCnt = 0;
    __syncthreads();

    const float thresh = g_rmin[row] + MARGIN;
    const uint4* srow = (const uint4*)(g_s + (size_t)row * K);

    for (int j = 0; j < K / (128 * 8); j++) {
        int u4i = tid + j * 128;
        uint4 u = srow[u4i];
        unsigned uw[4] = {u.x, u.y, u.z, u.w};
#pragma unroll
        for (int p = 0; p < 4; p++) {
            float2 f = __half22float2(*reinterpret_cast<const __half2*>(&uw[p]));
            if (f.x <= thresh) {
                int pos = atomicAdd(&sCnt, 1);
                if (pos < CAP) sCand[pos] = u4i * 8 + p * 2;
            }
            if (f.y <= thresh) {
                int pos = atomicAdd(&sCnt, 1);
                if (pos < CAP) sCand[pos] = u4i * 8 + p * 2 + 1;
            }
        }
    }
    __syncthreads();
    const int cnt = sCnt;

    const float zz   = g_zz[row];
    const float4* zp = (const float4*)(z + (size_t)row * DDIM);

    float v  = 3.4e38f;
    int   bi = 0x7FFFFFFF;

    if (cnt <= CAP) {
        for (int ci = tid; ci < cnt; ci += 128) {
            int k = sCand[ci];
            const float4* ep = (const float4*)(emb + (size_t)k * DDIM);
            float accd = 0.f;
#pragma unroll 4
            for (int d = 0; d < DDIM / 4; d++) {
                float4 za = zp[d], ea = ep[d];
                accd = fmaf(za.x, ea.x, accd);
                accd = fmaf(za.y, ea.y, accd);
                accd = fmaf(za.z, ea.z, accd);
                accd = fmaf(za.w, ea.w, accd);
            }
            float q = fmaf(-2.f, accd, zz) + g_ee[k];
            if (q < v || (q == v && k < bi)) { v = q; bi = k; }
        }
    } else {
        for (int k = tid; k < K; k += 128) {
            const float4* ep = (const float4*)(emb + (size_t)k * DDIM);
            float accd = 0.f;
#pragma unroll 4
            for (int d = 0; d < DDIM / 4; d++) {
                float4 za = zp[d], ea = ep[d];
                accd = fmaf(za.x, ea.x, accd);
                accd = fmaf(za.y, ea.y, accd);
                accd = fmaf(za.z, ea.z, accd);
                accd = fmaf(za.w, ea.w, accd);
            }
            float q = fmaf(-2.f, accd, zz) + g_ee[k];
            if (q < v || (q == v && k < bi)) { v = q; bi = k; }
        }
    }

    sv[tid] = v;
    si[tid] = bi;
    __syncthreads();
#pragma unroll
    for (int s = 64; s > 0; s >>= 1) {
        if (tid < s) {
            float ov = sv[tid + s];
            int   oi = si[tid + s];
            if (ov < sv[tid] || (ov == sv[tid] && oi < si[tid])) {
                sv[tid] = ov; si[tid] = oi;
            }
        }
        __syncthreads();
    }
    if (tid == 0) g_best[row] = si[0];
}

// ---- output + loss -------------------------------------------------------
__global__ void gather_loss_kernel(const float* __restrict__ z,
                                   const float* __restrict__ emb,
                                   float* __restrict__ out_zq,
                                   float* __restrict__ out_idx,
                                   int B)
{
    __shared__ double sred[128];
    const int tid = threadIdx.x;
    double lsum = 0.0;

    for (int r = 0; r < 32; r++) {
        int b   = blockIdx.x * 32 + r;
        int idx = g_best[b];
        if (tid == 0 && out_idx) out_idx[b] = (float)idx;

        float4 zv = ((const float4*)(z   + (size_t)b   * DDIM))[tid];
        float4 ev = ((const float4*)(emb + (size_t)idx * DDIM))[tid];
        float4 o;
        float dx;
        dx = ev.x - zv.x; o.x = zv.x + dx; lsum += (double)dx * (double)dx;
        dx = ev.y - zv.y; o.y = zv.y + dx; lsum += (double)dx * (double)dx;
        dx = ev.z - zv.z; o.z = zv.z + dx; lsum += (double)dx * (double)dx;
        dx = ev.w - zv.w; o.w = zv.w + dx; lsum += (double)dx * (double)dx;
        ((float4*)(out_zq + (size_t)b * DDIM))[tid] = o;
    }

    sred[tid] = lsum;
    __syncthreads();
#pragma unroll
    for (int s = 64; s > 0; s >>= 1) {
        if (tid < s) sred[tid] += sred[tid + s];
        __syncthreads();
    }
    if (tid == 0) g_part[blockIdx.x] = sred[0];
}

__global__ void finalize_kernel(float* __restrict__ out_loss, int nparts, double scale)
{
    __shared__ double sred[512];
    int tid = threadIdx.x;
    sred[tid] = (tid < nparts) ? g_part[tid] : 0.0;
    __syncthreads();
#pragma unroll
    for (int s = 256; s > 0; s >>= 1) {
        if (tid < s) sred[tid] += sred[tid + s];
        __syncthreads();
    }
    if (tid == 0) *out_loss = (float)(sred[0] * scale);
}

// -------------------------------------------------------------------------
extern "C" void kernel_launch(void* const* d_in, const int* in_sizes, int n_in,
                              void* d_out, int out_size)
{
    const float* z   = (const float*)d_in[0];
    const float* emb = (const float*)d_in[1];
    int B = in_sizes[0] / DDIM;   // 16384
    int K = in_sizes[1] / DDIM;   // 8192

    float* out      = (float*)d_out;
    float* out_zq   = out;
    float* out_idx  = ((size_t)out_size >= (size_t)B * DDIM + (size_t)B)
                        ? out + (size_t)B * DDIM : nullptr;
    float* out_loss = ((size_t)out_size >= (size_t)B * DDIM + (size_t)B + 1)
                        ? out + (size_t)B * DDIM + B : nullptr;

    __nv_bfloat16 *zb, *eb;
    cudaGetSymbolAddress((void**)&zb, g_zb);
    cudaGetSymbolAddress((void**)&eb, g_eb);

    static int smem_set = 0;
    const int dyn_smem = (2 * BUF_H + BM * STROW_H) * 2;   // 48128 B
    if (!smem_set) {
        cudaFuncSetAttribute(vq_phase1_kernel,
                             cudaFuncAttributeMaxDynamicSharedMemorySize, dyn_smem);
        smem_set = 1;
    }

    int nz4 = B * DDIM / 4, ne4 = K * DDIM / 4;
    to_bf16_kernel<<<(nz4 + 255) / 256, 256>>>(z, zb, nz4);
    to_bf16_kernel<<<(ne4 + 255) / 256, 256>>>(emb, eb, ne4);
    rowsq_kernel<<<((K + B) * 32 + 255) / 256, 256>>>(emb, z, K, B);

    vq_phase1_kernel<<<B / BM, 256, dyn_smem>>>(K);
    scan_rescue_kernel<<<B, 128>>>(z, emb, K);

    int gblocks = B / 32;
    gather_loss_kernel<<<gblocks, 128>>>(z, emb, out_zq, out_idx, B);
    if (out_loss)
        finalize_kernel<<<1, 512>>>(out_loss, gblocks, 1.25 / ((double)B * (double)DDIM));
}

// round 11
// speedup vs baseline: 7.4143x; 1.2313x over previous
#include <cuda_runtime.h>
#include <cuda_bf16.h>
#include <cuda_fp16.h>
#include <cstdint>
#include <cstddef>

// VectorQuantizer, two-phase:
//   Phase 1: bf16 ldmatrix+mma GEMM, BM=64 x BN=256 tiles, 4 warps with fat
//            64x64 warp tiles (halves smem bytes/MAC vs 32x32), 2 CTAs/SM ->
//            fp16 screen s[b,k] = ee - 2*G (256 MB) + per-row fp32 min.
//   Phase 2: per-row scan of the screen (final-min + MARGIN) -> compact
//            candidates -> exact fp32 rescue (bit-identical Round-2 chain).
// Output: [ z_q_st (B*512) | indices as float (B) | vq_loss (1) ]

#define DDIM 512
#define NB 16384
#define NK 8192
#define BM 64
#define BN 256

#define SA 40                      // smem row stride in halves (80B, LDSM conflict-free)
#define ABUF_H (64 * SA)           // A tile: 64 rows   (2560 halves)
#define BBUF_H (256 * SA)          // B tile: 256 rows  (10240 halves)
#define BUF_H  (ABUF_H + BBUF_H)   // 12800 halves per pipeline buffer
#define STAGE_OFF_H (2 * BUF_H)    // 25600
#define STROW_H 264                // stage row stride in halves (256 + 8 pad)

#define CAP 64
#define MARGIN 2e-3f

__device__ float  g_ee[NK];
__device__ float  g_zz[NB];
__device__ float  g_rmin[NB];
__device__ int    g_best[NB];
__device__ double g_part[512];

__device__ __nv_bfloat16 g_zb[NB * DDIM];
__device__ __nv_bfloat16 g_eb[NK * DDIM];
__device__ __half        g_s[(size_t)NB * NK];  // fp16 screen, 256 MB

// ---- helpers -------------------------------------------------------------
__device__ __forceinline__ unsigned smem_u32(const void* p)
{
    return (unsigned)__cvta_generic_to_shared(p);
}
__device__ __forceinline__ void cp16(__half* sdst, const void* gsrc)
{
    asm volatile("cp.async.ca.shared.global [%0], [%1], 16;\n"
                 :: "r"(smem_u32(sdst)), "l"(gsrc));
}
__device__ __forceinline__ void cp_commit() { asm volatile("cp.async.commit_group;\n"); }
__device__ __forceinline__ void cp_wait0()  { asm volatile("cp.async.wait_group 0;\n"); }

__device__ __forceinline__ void ldsm4(unsigned* r, unsigned addr)
{
    asm volatile("ldmatrix.sync.aligned.m8n8.x4.shared.b16 {%0,%1,%2,%3}, [%4];"
                 : "=r"(r[0]), "=r"(r[1]), "=r"(r[2]), "=r"(r[3]) : "r"(addr));
}
__device__ __forceinline__ void mma_bf16(float* c, const unsigned* a,
                                         unsigned b0, unsigned b1)
{
    asm volatile(
        "mma.sync.aligned.m16n8k16.row.col.f32.bf16.bf16.f32 "
        "{%0,%1,%2,%3}, {%4,%5,%6,%7}, {%8,%9}, {%0,%1,%2,%3};\n"
        : "+f"(c[0]), "+f"(c[1]), "+f"(c[2]), "+f"(c[3])
        : "r"(a[0]), "r"(a[1]), "r"(a[2]), "r"(a[3]), "r"(b0), "r"(b1));
}

// ---- prep ----------------------------------------------------------------
__global__ void to_bf16_kernel(const float* __restrict__ src,
                               __nv_bfloat16* __restrict__ dst, int n4)
{
    int i = blockIdx.x * blockDim.x + threadIdx.x;
    if (i >= n4) return;
    float4 v = ((const float4*)src)[i];
    __nv_bfloat162 p0 = __floats2bfloat162_rn(v.x, v.y);
    __nv_bfloat162 p1 = __floats2bfloat162_rn(v.z, v.w);
    uint2 w;
    w.x = *reinterpret_cast<unsigned*>(&p0);
    w.y = *reinterpret_cast<unsigned*>(&p1);
    ((uint2*)dst)[i] = w;
}

__global__ void rowsq_kernel(const float* __restrict__ emb,
                             const float* __restrict__ z,
                             int K, int B)
{
    int w    = (blockIdx.x * blockDim.x + threadIdx.x) >> 5;
    int lane = threadIdx.x & 31;
    if (w >= K + B) return;
    const float* src = (w < K) ? (emb + (size_t)w * DDIM)
                               : (z   + (size_t)(w - K) * DDIM);
    float s = 0.f;
#pragma unroll
    for (int t = 0; t < DDIM / 32; t++) {
        float x = src[lane + 32 * t];
        s = fmaf(x, x, s);
    }
#pragma unroll
    for (int off = 16; off > 0; off >>= 1)
        s += __shfl_xor_sync(0xFFFFFFFFu, s, off);
    if (lane == 0) {
        if (w < K) g_ee[w] = s;
        else       g_zz[w - K] = s;
    }
}

// ---- Phase 1: 128 thr = 4 warps (all warpN), warp tile 64x64, 2 CTAs/SM --
__global__ __launch_bounds__(128, 2)
void vq_phase1_kernel(int K)
{
    extern __shared__ __half smem[];
    __shared__ float sEE[BN];

    const int tid   = threadIdx.x;
    const int wid   = tid >> 5;
    const int lane  = tid & 31;
    const int g     = lane >> 2;
    const int t     = lane & 3;
    const int warpN = wid;           // 0..3, warp covers cols [warpN*64, +64)
    const int brow  = blockIdx.x * BM;

    float bestv[8];
#pragma unroll
    for (int a = 0; a < 8; a++) bestv[a] = 3.4e38f;

    // cp.async mapping
    int acr[2], acc_[2];               // A: 64 rows x 4 x 16B = 256 units, 2/thread
#pragma unroll
    for (int i = 0; i < 2; i++) {
        int idx = tid + i * 128;
        acr[i]  = idx >> 2;
        acc_[i] = (idx & 3) * 8;
    }
    int bcr[8], bcc[8];                // B: 256 rows x 4 x 16B = 1024 units, 8/thread
#pragma unroll
    for (int i = 0; i < 8; i++) {
        int idx = tid + i * 128;
        bcr[i] = idx >> 2;
        bcc[i] = (idx & 3) * 8;
    }

    // ldmatrix lane offsets (validated R6/R7/R9/R10)
    const int aRow = lane & 15;
    const int aCol = (lane >> 4) << 3;
    const int bRow = (lane & 7) + ((lane & 16) >> 1);
    const int bCol = lane & 8;

    const int NCH = (K / BN) * 16;    // 512

    // prologue: chunk 0 -> buffer 0
    {
        __half* bA = smem;
        __half* bB = smem + ABUF_H;
#pragma unroll
        for (int i = 0; i < 2; i++)
            cp16(bA + acr[i] * SA + acc_[i],
                 g_zb + (size_t)(brow + acr[i]) * DDIM + acc_[i]);
#pragma unroll
        for (int i = 0; i < 8; i++)
            cp16(bB + bcr[i] * SA + bcc[i],
                 g_eb + (size_t)bcr[i] * DDIM + bcc[i]);
        cp_commit();
    }

    float acc[4][8][4];
#pragma unroll
    for (int mt = 0; mt < 4; mt++)
#pragma unroll
        for (int nt = 0; nt < 8; nt++)
#pragma unroll
            for (int r = 0; r < 4; r++) acc[mt][nt][r] = 0.f;

    for (int c = 0; c < NCH; c++) {
        const int dch = c & 15;
        const int kt  = (c >> 4) * BN;
        __half* bA = smem + (c & 1) * BUF_H;
        __half* bB = bA + ABUF_H;

        cp_wait0();
        __syncthreads();

        if (dch == 0) {
            sEE[tid]       = g_ee[kt + tid];
            sEE[tid + 128] = g_ee[kt + tid + 128];
        }

        if (c + 1 < NCH) {
            const int ndb = ((c + 1) & 15) * 32;
            const int nkt = ((c + 1) >> 4) * BN;
            __half* nA = smem + ((c + 1) & 1) * BUF_H;
            __half* nB = nA + ABUF_H;
#pragma unroll
            for (int i = 0; i < 2; i++)
                cp16(nA + acr[i] * SA + acc_[i],
                     g_zb + (size_t)(brow + acr[i]) * DDIM + ndb + acc_[i]);
#pragma unroll
            for (int i = 0; i < 8; i++)
                cp16(nB + bcr[i] * SA + bcc[i],
                     g_eb + (size_t)(nkt + bcr[i]) * DDIM + ndb + bcc[i]);
            cp_commit();
        }

        // compute: 2 k16 steps, ldmatrix feeds
#pragma unroll
        for (int ks = 0; ks < 2; ks++) {
            const int kb = ks * 16;
            unsigned A[4][4], Bf[4][4];
#pragma unroll
            for (int mt = 0; mt < 4; mt++)
                ldsm4(A[mt], smem_u32(&bA[(mt * 16 + aRow) * SA + kb + aCol]));
#pragma unroll
            for (int np = 0; np < 4; np++)
                ldsm4(Bf[np], smem_u32(&bB[(warpN * 64 + np * 16 + bRow) * SA + kb + bCol]));
#pragma unroll
            for (int mt = 0; mt < 4; mt++)
#pragma unroll
                for (int nt = 0; nt < 8; nt++)
                    mma_bf16(acc[mt][nt], A[mt],
                             Bf[nt >> 1][(nt & 1) * 2], Bf[nt >> 1][(nt & 1) * 2 + 1]);
        }

        if (dch == 15) {
            __half* stage = smem + STAGE_OFF_H;
#pragma unroll
            for (int mt = 0; mt < 4; mt++)
#pragma unroll
                for (int i = 0; i < 2; i++) {
                    const int a = mt * 2 + i;
                    const int srow = mt * 16 + i * 8 + g;
                    float v = 3.4e38f;
#pragma unroll
                    for (int nt = 0; nt < 8; nt++) {
                        int col = warpN * 64 + nt * 8 + 2 * t;
                        float s0 = fmaf(-2.f, acc[mt][nt][i * 2 + 0], sEE[col]);
                        float s1 = fmaf(-2.f, acc[mt][nt][i * 2 + 1], sEE[col + 1]);
                        *(__half2*)&stage[srow * STROW_H + col] =
                            __floats2half2_rn(s0, s1);
                        float m = (s0 < s1) ? s0 : s1;
                        if (m < v) v = m;
                    }
#pragma unroll
                    for (int off = 1; off < 4; off <<= 1) {
                        float ov = __shfl_xor_sync(0xFFFFFFFFu, v, off);
                        if (ov < v) v = ov;
                    }
                    if (v < bestv[a]) bestv[a] = v;
                }
#pragma unroll
            for (int mt = 0; mt < 4; mt++)
#pragma unroll
                for (int nt = 0; nt < 8; nt++)
#pragma unroll
                    for (int r = 0; r < 4; r++) acc[mt][nt][r] = 0.f;

            __syncthreads();
            // cooperative store staging -> g_s (fp16): 64 rows x 32 float4 = 2048
#pragma unroll
            for (int i = 0; i < 16; i++) {
                int idx = tid + i * 128;
                int row = idx >> 5;
                int c8  = idx & 31;
                float4 v4 = *(const float4*)&stage[row * STROW_H + c8 * 8];
                *(float4*)&g_s[(size_t)(brow + row) * K + kt + c8 * 8] = v4;
            }
        }
    }

    // merge the four warpN quarters -> per-row min
    __syncthreads();
    float* sv = (float*)(smem + STAGE_OFF_H);   // [4][64]
    if (t == 0) {
#pragma unroll
        for (int a = 0; a < 8; a++) {
            int row = (a >> 1) * 16 + (a & 1) * 8 + g;
            sv[warpN * 64 + row] = bestv[a];
        }
    }
    __syncthreads();
    if (tid < BM) {
        float v0 = sv[tid];
        float v1 = sv[64 + tid];
        float v2 = sv[128 + tid];
        float v3 = sv[192 + tid];
        float m01 = (v1 < v0) ? v1 : v0;
        float m23 = (v3 < v2) ? v3 : v2;
        g_rmin[brow + tid] = (m23 < m01) ? m23 : m01;
    }
}

// ---- Phase 2: per-row scan + compact + exact rescue ----------------------
__global__ __launch_bounds__(128)
void scan_rescue_kernel(const float* __restrict__ z,
                        const float* __restrict__ emb, int K)
{
    __shared__ int   sCand[CAP];
    __shared__ int   sCnt;
    __shared__ float sv[128];
    __shared__ int   si[128];

    const int row = blockIdx.x;
    const int tid = threadIdx.x;

    if (tid == 0) sCnt = 0;
    __syncthreads();

    const float thresh = g_rmin[row] + MARGIN;
    const uint4* srow = (const uint4*)(g_s + (size_t)row * K);

    for (int j = 0; j < K / (128 * 8); j++) {
        int u4i = tid + j * 128;
        uint4 u = srow[u4i];
        unsigned uw[4] = {u.x, u.y, u.z, u.w};
#pragma unroll
        for (int p = 0; p < 4; p++) {
            float2 f = __half22float2(*reinterpret_cast<const __half2*>(&uw[p]));
            if (f.x <= thresh) {
                int pos = atomicAdd(&sCnt, 1);
                if (pos < CAP) sCand[pos] = u4i * 8 + p * 2;
            }
            if (f.y <= thresh) {
                int pos = atomicAdd(&sCnt, 1);
                if (pos < CAP) sCand[pos] = u4i * 8 + p * 2 + 1;
            }
        }
    }
    __syncthreads();
    const int cnt = sCnt;

    const float zz   = g_zz[row];
    const float4* zp = (const float4*)(z + (size_t)row * DDIM);

    float v  = 3.4e38f;
    int   bi = 0x7FFFFFFF;

    if (cnt <= CAP) {
        for (int ci = tid; ci < cnt; ci += 128) {
            int k = sCand[ci];
            const float4* ep = (const float4*)(emb + (size_t)k * DDIM);
            float accd = 0.f;
#pragma unroll 4
            for (int d = 0; d < DDIM / 4; d++) {
                float4 za = zp[d], ea = ep[d];
                accd = fmaf(za.x, ea.x, accd);
                accd = fmaf(za.y, ea.y, accd);
                accd = fmaf(za.z, ea.z, accd);
                accd = fmaf(za.w, ea.w, accd);
            }
            float q = fmaf(-2.f, accd, zz) + g_ee[k];
            if (q < v || (q == v && k < bi)) { v = q; bi = k; }
        }
    } else {
        for (int k = tid; k < K; k += 128) {
            const float4* ep = (const float4*)(emb + (size_t)k * DDIM);
            float accd = 0.f;
#pragma unroll 4
            for (int d = 0; d < DDIM / 4; d++) {
                float4 za = zp[d], ea = ep[d];
                accd = fmaf(za.x, ea.x, accd);
                accd = fmaf(za.y, ea.y, accd);
                accd = fmaf(za.z, ea.z, accd);
                accd = fmaf(za.w, ea.w, accd);
            }
            float q = fmaf(-2.f, accd, zz) + g_ee[k];
            if (q < v || (q == v && k < bi)) { v = q; bi = k; }
        }
    }

    sv[tid] = v;
    si[tid] = bi;
    __syncthreads();
#pragma unroll
    for (int s = 64; s > 0; s >>= 1) {
        if (tid < s) {
            float ov = sv[tid + s];
            int   oi = si[tid + s];
            if (ov < sv[tid] || (ov == sv[tid] && oi < si[tid])) {
                sv[tid] = ov; si[tid] = oi;
            }
        }
        __syncthreads();
    }
    if (tid == 0) g_best[row] = si[0];
}

// ---- output + loss -------------------------------------------------------
__global__ void gather_loss_kernel(const float* __restrict__ z,
                                   const float* __restrict__ emb,
                                   float* __restrict__ out_zq,
                                   float* __restrict__ out_idx,
                                   int B)
{
    __shared__ double sred[128];
    const int tid = threadIdx.x;
    double lsum = 0.0;

    for (int r = 0; r < 32; r++) {
        int b   = blockIdx.x * 32 + r;
        int idx = g_best[b];
        if (tid == 0 && out_idx) out_idx[b] = (float)idx;

        float4 zv = ((const float4*)(z   + (size_t)b   * DDIM))[tid];
        float4 ev = ((const float4*)(emb + (size_t)idx * DDIM))[tid];
        float4 o;
        float dx;
        dx = ev.x - zv.x; o.x = zv.x + dx; lsum += (double)dx * (double)dx;
        dx = ev.y - zv.y; o.y = zv.y + dx; lsum += (double)dx * (double)dx;
        dx = ev.z - zv.z; o.z = zv.z + dx; lsum += (double)dx * (double)dx;
        dx = ev.w - zv.w; o.w = zv.w + dx; lsum += (double)dx * (double)dx;
        ((float4*)(out_zq + (size_t)b * DDIM))[tid] = o;
    }

    sred[tid] = lsum;
    __syncthreads();
#pragma unroll
    for (int s = 64; s > 0; s >>= 1) {
        if (tid < s) sred[tid] += sred[tid + s];
        __syncthreads();
    }
    if (tid == 0) g_part[blockIdx.x] = sred[0];
}

__global__ void finalize_kernel(float* __restrict__ out_loss, int nparts, double scale)
{
    __shared__ double sred[512];
    int tid = threadIdx.x;
    sred[tid] = (tid < nparts) ? g_part[tid] : 0.0;
    __syncthreads();
#pragma unroll
    for (int s = 256; s > 0; s >>= 1) {
        if (tid < s) sred[tid] += sred[tid + s];
        __syncthreads();
    }
    if (tid == 0) *out_loss = (float)(sred[0] * scale);
}

// -------------------------------------------------------------------------
extern "C" void kernel_launch(void* const* d_in, const int* in_sizes, int n_in,
                              void* d_out, int out_size)
{
    const float* z   = (const float*)d_in[0];
    const float* emb = (const float*)d_in[1];
    int B = in_sizes[0] / DDIM;   // 16384
    int K = in_sizes[1] / DDIM;   // 8192

    float* out      = (float*)d_out;
    float* out_zq   = out;
    float* out_idx  = ((size_t)out_size >= (size_t)B * DDIM + (size_t)B)
                        ? out + (size_t)B * DDIM : nullptr;
    float* out_loss = ((size_t)out_size >= (size_t)B * DDIM + (size_t)B + 1)
                        ? out + (size_t)B * DDIM + B : nullptr;

    __nv_bfloat16 *zb, *eb;
    cudaGetSymbolAddress((void**)&zb, g_zb);
    cudaGetSymbolAddress((void**)&eb, g_eb);

    static int smem_set = 0;
    const int dyn_smem = (2 * BUF_H + BM * STROW_H) * 2;   // 84992 B
    if (!smem_set) {
        cudaFuncSetAttribute(vq_phase1_kernel,
                             cudaFuncAttributeMaxDynamicSharedMemorySize, dyn_smem);
        smem_set = 1;
    }

    int nz4 = B * DDIM / 4, ne4 = K * DDIM / 4;
    to_bf16_kernel<<<(nz4 + 255) / 256, 256>>>(z, zb, nz4);
    to_bf16_kernel<<<(ne4 + 255) / 256, 256>>>(emb, eb, ne4);
    rowsq_kernel<<<((K + B) * 32 + 255) / 256, 256>>>(emb, z, K, B);

    vq_phase1_kernel<<<B / BM, 128, dyn_smem>>>(K);
    scan_rescue_kernel<<<B, 128>>>(z, emb, K);

    int gblocks = B / 32;
    gather_loss_kernel<<<gblocks, 128>>>(z, emb, out_zq, out_idx, B);
    if (out_loss)
        finalize_kernel<<<1, 512>>>(out_loss, gblocks, 1.25 / ((double)B * (double)DDIM));
}